// round 1
// baseline (speedup 1.0000x reference)
#include <cuda_runtime.h>

// RiRoIAlign for GB300.
// features: (B=2, Ctot=256, H=256, W=256) fp32
// rois: (512, 6) fp32 = [batch, cx, cy, w, h, theta]
// out: (512, 256, 7, 7) fp32, channel index = c*8 + o  (C=32 channels, O=8 orientations)
//
// Key identity: ind_rot_p[o] == ind_rot[(o+1)%8], so per (roi, channel, bin)
// we accumulate 8 plane values once and blend pairs with (r_var, l_var).

#define HH 256
#define WW 256
#define CT 256
#define OO 8
#define NBIN 49   // 7x7
#define NS 196    // 7*2*7*2 sample points

__global__ __launch_bounds__(256, 4)
void riroi_kernel(const float* __restrict__ features,
                  const float* __restrict__ rois,
                  float* __restrict__ out)
{
    __shared__ int4   soff[NS];   // 4 bilinear tap offsets (y*W+x)
    __shared__ float4 swt[NS];    // 4 bilinear weights (incl. valid mask)
    __shared__ float  acc[OO * NBIN];

    const int r   = blockIdx.x;
    const int cg  = blockIdx.y;   // channel group: channels [cg*8, cg*8+8)
    const int tid = threadIdx.x;

    // ---- ROI parameters (computed redundantly per thread; cheap) ----
    const float b_f  = rois[r * 6 + 0];
    const float cwv  = rois[r * 6 + 1] * 0.125f;
    const float chv  = rois[r * 6 + 2] * 0.125f;
    const float rw   = fmaxf(rois[r * 6 + 3] * 0.125f, 1.0f);
    const float rh   = fmaxf(rois[r * 6 + 4] * 0.125f, 1.0f);
    const float th   = rois[r * 6 + 5];
    const int   b    = (int)b_f;

    const float st = sinf(th);
    const float ct = cosf(th);

    const float indf   = (th * 8.0f) / 6.283185307179586f;
    const float indflo = floorf(indf);
    const float lv     = indf - indflo;       // l_var
    const float rv     = 1.0f - lv;           // r_var
    int ind = (int)indflo;
    ind = ((ind % 8) + 8) % 8;

    const float bin_h = rh / 7.0f;
    const float bin_w = rw / 7.0f;

    // ---- sample geometry: 196 samples, flattened order (py, gy, px, gx) ----
    if (tid < NS) {
        const int s  = tid;
        const int gx = s & 1;
        const int px = (s >> 1) % 7;
        const int gy = (s / 14) & 1;
        const int py = s / 28;

        const float yy = -rh * 0.5f + ((float)py + ((float)gy + 0.5f) * 0.5f) * bin_h;
        const float xx = -rw * 0.5f + ((float)px + ((float)gx + 0.5f) * 0.5f) * bin_w;

        const float x = xx * ct - yy * st + cwv;
        const float y = xx * st + yy * ct + chv;

        const bool valid = (y > -1.0f) && (y < 256.0f) && (x > -1.0f) && (x < 256.0f);

        const float yc = fmaxf(y, 0.0f);
        const float xc = fmaxf(x, 0.0f);
        int yl = (int)yc;
        int xl = (int)xc;
        int yh, xh;
        float yv, xv;
        if (yl >= HH - 1) { yl = HH - 1; yh = HH - 1; yv = (float)(HH - 1); }
        else              { yh = yl + 1;              yv = yc; }
        if (xl >= WW - 1) { xl = WW - 1; xh = WW - 1; xv = (float)(WW - 1); }
        else              { xh = xl + 1;              xv = xc; }

        const float ly = yv - (float)yl;
        const float lx = xv - (float)xl;
        const float hy = 1.0f - ly;
        const float hx = 1.0f - lx;
        const float vm = valid ? 1.0f : 0.0f;

        swt[s]  = make_float4(hy * hx * vm, hy * lx * vm, ly * hx * vm, ly * lx * vm);
        soff[s] = make_int4(yl * WW + xl, yl * WW + xh, yh * WW + xl, yh * WW + xh);
    }
    __syncthreads();

    // base pointer: features[b, (cg*8 + cc)*8 + plane, :, :]
    const float* fb = features + ((size_t)b * CT + (size_t)cg * 8 * OO) * (size_t)(HH * WW);

    for (int cc = 0; cc < 8; ++cc) {
        const float* cb = fb + (size_t)cc * OO * HH * WW;

        // accumulate: item = plane*49 + bin; each item sums 4 samples x 4 taps
        for (int it = tid; it < OO * NBIN; it += 256) {
            const int plane = it / NBIN;
            const int bin   = it - plane * NBIN;
            const int py    = bin / 7;
            const int px    = bin - py * 7;
            const float* pl = cb + plane * (HH * WW);

            float a = 0.0f;
            #pragma unroll
            for (int gy = 0; gy < 2; ++gy) {
                #pragma unroll
                for (int gx = 0; gx < 2; ++gx) {
                    const int s = ((py * 2 + gy) * 7 + px) * 2 + gx;
                    const int4   o = soff[s];
                    const float4 w = swt[s];
                    a += w.x * __ldg(pl + o.x)
                       + w.y * __ldg(pl + o.y)
                       + w.z * __ldg(pl + o.z)
                       + w.w * __ldg(pl + o.w);
                }
            }
            acc[it] = a;
        }
        __syncthreads();

        // orientation mix + write: out[r, c*8+o, py, px], c = cg*8+cc
        const int c = cg * 8 + cc;
        float* ob = out + ((size_t)r * CT + (size_t)c * OO) * (size_t)NBIN;
        for (int it = tid; it < OO * NBIN; it += 256) {
            const int o   = it / NBIN;
            const int bin = it - o * NBIN;
            const int p0  = (o - ind + 8) & 7;
            const int p1  = (p0 + 1) & 7;
            ob[it] = 0.25f * (rv * acc[p0 * NBIN + bin] + lv * acc[p1 * NBIN + bin]);
        }
        __syncthreads();
    }
}

extern "C" void kernel_launch(void* const* d_in, const int* in_sizes, int n_in,
                              void* d_out, int out_size)
{
    const float* features = (const float*)d_in[0];
    const float* rois     = (const float*)d_in[1];
    float*       out      = (float*)d_out;

    const int R = in_sizes[1] / 6;   // 512
    dim3 grid((unsigned)R, 4);
    riroi_kernel<<<grid, 256>>>(features, rois, out);
}